// round 15
// baseline (speedup 1.0000x reference)
#include <cuda_runtime.h>
#include <cuda_bf16.h>
#include <math.h>

// Clockwork RNN, hierarchically decomposed.
// B=128, T=512, I=2, H=1024, NM=8, MS=128.
// Round 15: R13 pipelined tensor GEMM piece (best) for both urgent and
// fused-deferred launches; pout module-0 fused into assemble (warp-per-(b,t));
// single pout launch for modules 1-7 on stream1.

#define NB   128
#define NT   512
#define NH   1024
#define NMOD 8
#define MSZ  128

__constant__ int c_TOFF[8] = {0, 513, 770, 899, 964, 997, 1014, 1023};
__constant__ int c_S[8] = {513, 257, 129, 65, 33, 17, 9, 5};
__constant__ long long c_GOFF[8] = {0, 0, 4210688, 8437760, 11632640,
                                    13795328, 15187968, 16072704};

__device__ __nv_bfloat16 g_trajH[16842752];
__device__ __nv_bfloat16 g_trajL[16842752];
__device__ __nv_bfloat16 g_WHi[NH * NH];
__device__ __nv_bfloat16 g_WLo[NH * NH];
__device__ float g_G[16646144];
__device__ float g_pout[1028 * NB * 2];

// helpers -------------------------------------------------------------------
__device__ __forceinline__ void fma2(unsigned long long& d,
                                     unsigned long long a,
                                     unsigned long long b) {
    asm("fma.rn.f32x2 %0, %1, %2, %0;" : "+l"(d) : "l"(a), "l"(b));
}
__device__ __forceinline__ unsigned long long add2(unsigned long long a,
                                                   unsigned long long b) {
    unsigned long long d;
    asm("add.rn.f32x2 %0, %1, %2;" : "=l"(d) : "l"(a), "l"(b));
    return d;
}
union U4 { float4 f; unsigned long long u[2]; };
union U2 { unsigned long long u; float2 f; };

__device__ __forceinline__ float fast_tanh(float v) {
    float e = __expf(2.f * v);
    return 1.f - __fdividef(2.f, e + 1.f);
}

__device__ __forceinline__ void cp16(unsigned int dst, const void* src) {
    asm volatile("cp.async.ca.shared.global [%0], [%1], 16;"
                 :: "r"(dst), "l"(src));
}
__device__ __forceinline__ void cp_commit() {
    asm volatile("cp.async.commit_group;");
}
__device__ __forceinline__ void cp_wait1() {
    asm volatile("cp.async.wait_group 1;" ::: "memory");
}
__device__ __forceinline__ void cp_wait0() {
    asm volatile("cp.async.wait_group 0;" ::: "memory");
}
__device__ __forceinline__ void ldm4(unsigned int& r0, unsigned int& r1,
                                     unsigned int& r2, unsigned int& r3,
                                     unsigned int addr) {
    asm volatile("ldmatrix.sync.aligned.m8n8.x4.shared.b16 {%0,%1,%2,%3}, [%4];"
                 : "=r"(r0), "=r"(r1), "=r"(r2), "=r"(r3) : "r"(addr));
}
__device__ __forceinline__ void mma16816(float* c, const unsigned int* a,
                                         unsigned int b0, unsigned int b1) {
    asm volatile(
        "mma.sync.aligned.m16n8k16.row.col.f32.bf16.bf16.f32 "
        "{%0,%1,%2,%3}, {%4,%5,%6,%7}, {%8,%9}, {%0,%1,%2,%3};"
        : "+f"(c[0]), "+f"(c[1]), "+f"(c[2]), "+f"(c[3])
        : "r"(a[0]), "r"(a[1]), "r"(a[2]), "r"(a[3]), "r"(b0), "r"(b1));
}

// ---------------------------------------------------------------------------
__global__ void wsplit_kernel(const float* __restrict__ W_hh) {
    const int i = (blockIdx.x * 256 + threadIdx.x) * 4;
    const float4 w = *(const float4*)(W_hh + i);
    __nv_bfloat16 h0 = __float2bfloat16(w.x), h1 = __float2bfloat16(w.y);
    __nv_bfloat16 h2 = __float2bfloat16(w.z), h3 = __float2bfloat16(w.w);
    *(__nv_bfloat162*)(g_WHi + i)     = __nv_bfloat162(h0, h1);
    *(__nv_bfloat162*)(g_WHi + i + 2) = __nv_bfloat162(h2, h3);
    *(__nv_bfloat162*)(g_WLo + i) = __nv_bfloat162(
        __float2bfloat16(w.x - __bfloat162float(h0)),
        __float2bfloat16(w.y - __bfloat162float(h1)));
    *(__nv_bfloat162*)(g_WLo + i + 2) = __nv_bfloat162(
        __float2bfloat16(w.z - __bfloat162float(h2)),
        __float2bfloat16(w.w - __bfloat162float(h3)));
}

// ---------------------------------------------------------------------------
// Sequential diagonal chain for module M (R13 version).
// ---------------------------------------------------------------------------
template <int M>
__global__ __launch_bounds__(MSZ, 1) void chain_kernel(
    const float* __restrict__ x,
    const float* __restrict__ W_ih,
    const float* __restrict__ W_hh,
    const float* __restrict__ enc_w) {
    const int b = blockIdx.x;
    const int r = threadIdx.x;
    const int mbase = M * MSZ;
    __shared__ float h_s[2][MSZ];
    __shared__ float Wst[64][132];

    unsigned long long Wp[MSZ / 2];
#pragma unroll
    for (int pass = 0; pass < 2; pass++) {
#pragma unroll
        for (int i = 0; i < 16; i++) {
            const int idx = i * 128 + r;
            const int row = idx >> 5;
            const int c4 = idx & 31;
            *(float4*)&Wst[row][c4 * 4] =
                *(const float4*)(W_hh +
                                 (size_t)(mbase + pass * 64 + row) * NH +
                                 mbase + c4 * 4);
        }
        __syncthreads();
        if ((r >> 6) == pass) {
            const int rr = r & 63;
#pragma unroll
            for (int c4 = 0; c4 < 32; c4++) {
                U4 w;
                w.f = *(const float4*)&Wst[rr][c4 * 4];
                Wp[2 * c4 + 0] = w.u[0];
                Wp[2 * c4 + 1] = w.u[1];
            }
        }
        __syncthreads();
    }

    const float wih0 = W_ih[(mbase + r) * 2 + 0];
    const float wih1 = W_ih[(mbase + r) * 2 + 1];

    const float x00 = x[(size_t)b * (NT + 1) * 2 + 0];
    const float x01 = x[(size_t)b * (NT + 1) * 2 + 1];
    const float h0v = x00 * enc_w[(mbase + r) * 2 + 0] +
                      x01 * enc_w[(mbase + r) * 2 + 1];
    const size_t tbase = ((size_t)c_TOFF[M] * NB + b) * MSZ;
    h_s[0][r] = h0v;
    {
        const __nv_bfloat16 hi = __float2bfloat16(h0v);
        g_trajH[tbase + r] = hi;
        g_trajL[tbase + r] = __float2bfloat16(h0v - __bfloat162float(hi));
    }
    __syncthreads();

    const int K = NT >> M;
    constexpr int NG = (NMOD - 1 - M) > 0 ? (NMOD - 1 - M) : 1;

    const float* gp[NG];
    float gg[NG];
#pragma unroll
    for (int mp = M + 1; mp < NMOD; mp++) {
        gp[mp - M - 1] = g_G + c_GOFF[mp] + (size_t)b * (mp * MSZ) +
                         mbase + r;
        gg[mp - M - 1] = *gp[mp - M - 1];
    }

    float xn0 = x[((size_t)b * (NT + 1) + 1) * 2 + 0];
    float xn1 = x[((size_t)b * (NT + 1) + 1) * 2 + 1];

    int p = 0;
    for (int k = 0; k < K; k++) {
        float gsum = xn0 * wih0 + xn1 * wih1;
#pragma unroll
        for (int mp = M + 1; mp < NMOD; mp++) gsum += gg[mp - M - 1];

        const int t2 = (k + 1) << M;
        float xt0 = 0.f, xt1 = 0.f;
        if (k + 1 < K) {
            xt0 = x[((size_t)b * (NT + 1) + (t2 + 1)) * 2 + 0];
            xt1 = x[((size_t)b * (NT + 1) + (t2 + 1)) * 2 + 1];
        }
        float gt[NG];
#pragma unroll
        for (int mp = M + 1; mp < NMOD; mp++) {
            const int i = mp - M - 1;
            const bool trig = (((t2 - 1) & ((1 << mp) - 1)) < (1 << M));
            if (trig) {
                gp[i] += (size_t)NB * mp * MSZ;
                gt[i] = __ldg(gp[i]);
            } else {
                gt[i] = gg[i];
            }
        }

        unsigned long long acc[8] = {0, 0, 0, 0, 0, 0, 0, 0};
        const float4* h4 = (const float4*)h_s[p];
#pragma unroll
        for (int c4 = 0; c4 < MSZ / 4; c4++) {
            U4 hv;
            hv.f = h4[c4];
            fma2(acc[(2 * c4) & 7], Wp[2 * c4], hv.u[0]);
            fma2(acc[(2 * c4 + 1) & 7], Wp[2 * c4 + 1], hv.u[1]);
        }
        acc[0] = add2(acc[0], acc[1]);
        acc[2] = add2(acc[2], acc[3]);
        acc[4] = add2(acc[4], acc[5]);
        acc[6] = add2(acc[6], acc[7]);
        acc[0] = add2(acc[0], acc[2]);
        acc[4] = add2(acc[4], acc[6]);
        acc[0] = add2(acc[0], acc[4]);
        U2 a;
        a.u = acc[0];
        const float hn = fast_tanh(a.f.x + a.f.y + gsum);

        h_s[p ^ 1][r] = hn;
        const size_t so = tbase + (size_t)(k + 1) * (NB * MSZ) + r;
        const __nv_bfloat16 hi = __float2bfloat16(hn);
        g_trajH[so] = hi;
        g_trajL[so] = __float2bfloat16(hn - __bfloat162float(hi));
        __syncthreads();
        p ^= 1;

        xn0 = xt0; xn1 = xt1;
#pragma unroll
        for (int mp = M + 1; mp < NMOD; mp++) gg[mp - M - 1] = gt[mp - M - 1];
    }
}

// ---------------------------------------------------------------------------
// Pipelined tensor GEMM piece body (R13 champion): 64x64 tile, 128 thr,
// 8 K-chunks of 16, fused bf16-split (24 mma/chunk), 3-stage cp.async ring,
// one barrier per chunk.
// ---------------------------------------------------------------------------
__device__ __forceinline__ void g_piece_body(int mp, int tgt,
                                             int tilex, int tiley) {
    __shared__ __align__(16) __nv_bfloat16 AH[3][64][24];
    __shared__ __align__(16) __nv_bfloat16 AL[3][64][24];
    __shared__ __align__(16) __nv_bfloat16 BH[3][64][24];
    __shared__ __align__(16) __nv_bfloat16 BL[3][64][24];
    const int N = mp * MSZ;
    float* C = g_G + c_GOFF[mp] + tgt * MSZ;
    const int row0 = tilex * 64;
    const int n0 = tiley * 64;
    const int tid = threadIdx.x;
    const int w = tid >> 5;
    const int l = tid & 31;

    const size_t abase = (size_t)c_TOFF[mp] * (NB * MSZ);
    const __nv_bfloat16* AHsrc = g_trajH + abase;
    const __nv_bfloat16* ALsrc = g_trajL + abase;

    const int crow = tid >> 1, half = tid & 1;
    const unsigned int sAH =
        (unsigned int)__cvta_generic_to_shared(&AH[0][crow][half * 8]);
    const unsigned int sAL =
        (unsigned int)__cvta_generic_to_shared(&AL[0][crow][half * 8]);
    const unsigned int sBH =
        (unsigned int)__cvta_generic_to_shared(&BH[0][crow][half * 8]);
    const unsigned int sBL =
        (unsigned int)__cvta_generic_to_shared(&BL[0][crow][half * 8]);
    const unsigned int STG = 64 * 24 * 2;

    const size_t aoff = (size_t)(row0 + crow) * MSZ + half * 8;
    const size_t boff = (size_t)(tgt * MSZ + n0 + crow) * NH + mp * MSZ +
                        half * 8;

    #define LOAD_CHUNK(st, c)                                   \
        do {                                                    \
            cp16(sAH + (st) * STG, AHsrc + aoff + (c) * 16);    \
            cp16(sAL + (st) * STG, ALsrc + aoff + (c) * 16);    \
            cp16(sBH + (st) * STG, g_WHi + boff + (c) * 16);    \
            cp16(sBL + (st) * STG, g_WLo + boff + (c) * 16);    \
            cp_commit();                                        \
        } while (0)

    LOAD_CHUNK(0, 0);
    LOAD_CHUNK(1, 1);

    const int rowA = l & 15, kOffA = (l >> 4) * 8;
    const unsigned int aAddrH = (unsigned int)__cvta_generic_to_shared(
        &AH[0][w * 16 + rowA][kOffA]);
    const unsigned int aAddrL = (unsigned int)__cvta_generic_to_shared(
        &AL[0][w * 16 + rowA][kOffA]);
    const int gB = l >> 3, r8 = l & 7;
    const int nB = (gB >> 1) * 8 + r8, kOffB = (gB & 1) * 8;
    unsigned int bAddrH[4], bAddrL[4];
#pragma unroll
    for (int j = 0; j < 4; j++) {
        bAddrH[j] = (unsigned int)__cvta_generic_to_shared(
            &BH[0][j * 16 + nB][kOffB]);
        bAddrL[j] = (unsigned int)__cvta_generic_to_shared(
            &BL[0][j * 16 + nB][kOffB]);
    }

    float acc[8][4];
#pragma unroll
    for (int i = 0; i < 8; i++)
#pragma unroll
        for (int j = 0; j < 4; j++) acc[i][j] = 0.f;

#pragma unroll
    for (int c = 0; c < 8; c++) {
        if (c < 7) cp_wait1(); else cp_wait0();
        __syncthreads();
        if (c + 2 < 8) LOAD_CHUNK((c + 2) % 3, c + 2);

        const unsigned int so = (c % 3) * STG;
        unsigned int ah[4], al[4];
        ldm4(ah[0], ah[1], ah[2], ah[3], aAddrH + so);
        ldm4(al[0], al[1], al[2], al[3], aAddrL + so);
#pragma unroll
        for (int j = 0; j < 4; j++) {
            unsigned int h0, h1, h2, h3, q0, q1, q2, q3;
            ldm4(h0, h1, h2, h3, bAddrH[j] + so);
            ldm4(q0, q1, q2, q3, bAddrL[j] + so);
            mma16816(acc[2 * j], ah, h0, h1);
            mma16816(acc[2 * j + 1], ah, h2, h3);
            mma16816(acc[2 * j], ah, q0, q1);
            mma16816(acc[2 * j + 1], ah, q2, q3);
            mma16816(acc[2 * j], al, h0, h1);
            mma16816(acc[2 * j + 1], al, h2, h3);
        }
    }

    const int orow = row0 + w * 16 + (l >> 2);
    const int ocol = n0 + 2 * (l & 3);
#pragma unroll
    for (int cb = 0; cb < 8; cb++) {
        float2 v0 = {acc[cb][0], acc[cb][1]};
        float2 v1 = {acc[cb][2], acc[cb][3]};
        *(float2*)&C[(size_t)orow * N + ocol + cb * 8] = v0;
        *(float2*)&C[(size_t)(orow + 8) * N + ocol + cb * 8] = v1;
    }
    #undef LOAD_CHUNK
}

// urgent piece: one (mp, tgt)
__global__ __launch_bounds__(128, 4) void g_tcp(int mp, int tgt) {
    g_piece_body(mp, tgt, blockIdx.x, blockIdx.y);
}

// fused deferred pieces for target tau: blockIdx.z -> mp = tau+2+z
__global__ __launch_bounds__(128, 4) void g_tcd(int tau) {
    const int mp = tau + 2 + blockIdx.z;
    if ((int)blockIdx.x >= 2 * c_S[mp]) return;
    g_piece_body(mp, tau, blockIdx.x, blockIdx.y);
}

// ---------------------------------------------------------------------------
// fc partials for modules 1..7 (gs 513..1027); module looked up per state.
// ---------------------------------------------------------------------------
__global__ __launch_bounds__(256) void pout_kernel(
    const float* __restrict__ fc_w, int gs0) {
    const int gs = gs0 + blockIdx.x;
    const int warp = threadIdx.x >> 5;
    const int lane = threadIdx.x & 31;
    int m = 0;
#pragma unroll
    for (int j = 1; j < 8; j++)
        if (gs >= c_TOFF[j]) m = j;
    const int col = m * MSZ + lane * 4;
    const float4 w0 = *(const float4*)(fc_w + col);
    const float4 w1 = *(const float4*)(fc_w + NH + col);
    const size_t sbase = (size_t)gs * (NB * MSZ);

    for (int b = warp; b < NB; b += 8) {
        const size_t o = sbase + (size_t)b * MSZ + lane * 4;
        const __nv_bfloat162 h0 = *(const __nv_bfloat162*)(g_trajH + o);
        const __nv_bfloat162 h1 = *(const __nv_bfloat162*)(g_trajH + o + 2);
        const __nv_bfloat162 l0 = *(const __nv_bfloat162*)(g_trajL + o);
        const __nv_bfloat162 l1 = *(const __nv_bfloat162*)(g_trajL + o + 2);
        const float vx = __low2float(h0) + __low2float(l0);
        const float vy = __high2float(h0) + __high2float(l0);
        const float vz = __low2float(h1) + __low2float(l1);
        const float vw = __high2float(h1) + __high2float(l1);
        float a0 = vx * w0.x + vy * w0.y + vz * w0.z + vw * w0.w;
        float a1 = vx * w1.x + vy * w1.y + vz * w1.z + vw * w1.w;
#pragma unroll
        for (int off = 16; off > 0; off >>= 1) {
            a0 += __shfl_xor_sync(0xffffffffu, a0, off);
            a1 += __shfl_xor_sync(0xffffffffu, a1, off);
        }
        if (lane == 0) {
            g_pout[((size_t)gs * NB + b) * 2 + 0] = a0;
            g_pout[((size_t)gs * NB + b) * 2 + 1] = a1;
        }
    }
}

// ---------------------------------------------------------------------------
// Fused assemble: warp per (b,t). Lanes compute the module-0 dot slice;
// lanes 1..7 additionally add module-m pout pairs; lane 0 adds fc_b.
// Butterfly reduce sums everything; lane 0 stores the float2.
// ---------------------------------------------------------------------------
__global__ __launch_bounds__(256) void assemble_fused(
    const float* __restrict__ fc_w, const float* __restrict__ fc_b,
    float* __restrict__ out) {
    const int widx = blockIdx.x * 8 + (threadIdx.x >> 5);   // 0..65535
    const int lane = threadIdx.x & 31;
    const int b = widx >> 9;
    const int t = widx & 511;

    // module-0 dot slice (state gs = t+1, cols lane*4..lane*4+3)
    const size_t o = (size_t)(t + 1) * (NB * MSZ) + (size_t)b * MSZ + lane * 4;
    const __nv_bfloat162 h0 = *(const __nv_bfloat162*)(g_trajH + o);
    const __nv_bfloat162 h1 = *(const __nv_bfloat162*)(g_trajH + o + 2);
    const __nv_bfloat162 l0 = *(const __nv_bfloat162*)(g_trajL + o);
    const __nv_bfloat162 l1 = *(const __nv_bfloat162*)(g_trajL + o + 2);
    const float vx = __low2float(h0) + __low2float(l0);
    const float vy = __high2float(h0) + __high2float(l0);
    const float vz = __low2float(h1) + __low2float(l1);
    const float vw = __high2float(h1) + __high2float(l1);
    const float4 w0 = *(const float4*)(fc_w + lane * 4);
    const float4 w1 = *(const float4*)(fc_w + NH + lane * 4);
    float a0 = vx * w0.x + vy * w0.y + vz * w0.z + vw * w0.w;
    float a1 = vx * w1.x + vy * w1.y + vz * w1.z + vw * w1.w;

    // lanes 1..7: add module-m pout pair; lane 0: add bias
    if (lane >= 1 && lane <= 7) {
        const int m = lane;
        const int gs = c_TOFF[m] + (t >> m) + 1;
        const float2 pv = *(const float2*)&g_pout[((size_t)gs * NB + b) * 2];
        a0 += pv.x;
        a1 += pv.y;
    } else if (lane == 0) {
        a0 += fc_b[0];
        a1 += fc_b[1];
    }

#pragma unroll
    for (int off = 16; off > 0; off >>= 1) {
        a0 += __shfl_xor_sync(0xffffffffu, a0, off);
        a1 += __shfl_xor_sync(0xffffffffu, a1, off);
    }
    if (lane == 0) {
        float2 v = {a0, a1};
        *(float2*)&out[(size_t)widx * 2] = v;
    }
}

// ---------------------------------------------------------------------------
static const int h_S[8] = {513, 257, 129, 65, 33, 17, 9, 5};

extern "C" void kernel_launch(void* const* d_in, const int* in_sizes, int n_in,
                              void* d_out, int out_size) {
    const float* x     = (const float*)d_in[0];
    const float* W_ih  = (const float*)d_in[1];
    const float* W_hh  = (const float*)d_in[2];
    const float* fc_w  = (const float*)d_in[3];
    const float* fc_b  = (const float*)d_in[4];
    const float* enc_w = (const float*)d_in[5];
    float* out = (float*)d_out;

    static cudaStream_t s1 = nullptr;
    static cudaEvent_t evFork, evJoin, wEv, cEv[8], tEv[8];
    if (!s1) {
        cudaStreamCreateWithFlags(&s1, cudaStreamNonBlocking);
        cudaEventCreateWithFlags(&evFork, cudaEventDisableTiming);
        cudaEventCreateWithFlags(&evJoin, cudaEventDisableTiming);
        cudaEventCreateWithFlags(&wEv, cudaEventDisableTiming);
        for (int i = 0; i < 8; i++) {
            cudaEventCreateWithFlags(&cEv[i], cudaEventDisableTiming);
            cudaEventCreateWithFlags(&tEv[i], cudaEventDisableTiming);
        }
    }
    cudaStream_t s0 = 0;

    cudaEventRecord(evFork, s0);
    cudaStreamWaitEvent(s1, evFork, 0);

    #define RUN_CHAIN(M) chain_kernel<M><<<NB, MSZ, 0, s0>>>(x, W_ih, W_hh, enc_w)
    #define URGENT(MP)   g_tcp<<<dim3(2 * h_S[MP], 2), 128, 0, s0>>>(MP, (MP) - 1)
    #define DEFERT(TAU)  g_tcd<<<dim3(2 * h_S[(TAU) + 2], 2, 6 - (TAU)), 128, 0, s1>>>(TAU)

    wsplit_kernel<<<1024, 256, 0, s1>>>(W_hh);
    cudaEventRecord(wEv, s1);

    RUN_CHAIN(7);  cudaEventRecord(cEv[7], s0);
    cudaStreamWaitEvent(s0, wEv, 0);
    URGENT(7);

    cudaStreamWaitEvent(s1, cEv[7], 0);
    DEFERT(5);  cudaEventRecord(tEv[5], s1);            // target 5 (mp=7)

    RUN_CHAIN(6);  cudaEventRecord(cEv[6], s0);
    URGENT(6);

    cudaStreamWaitEvent(s1, cEv[6], 0);
    DEFERT(4);  cudaEventRecord(tEv[4], s1);            // target 4 (mp=6,7)

    cudaStreamWaitEvent(s0, tEv[5], 0);
    RUN_CHAIN(5);  cudaEventRecord(cEv[5], s0);
    URGENT(5);

    cudaStreamWaitEvent(s1, cEv[5], 0);
    DEFERT(3);  cudaEventRecord(tEv[3], s1);            // target 3 (mp=5..7)

    cudaStreamWaitEvent(s0, tEv[4], 0);
    RUN_CHAIN(4);  cudaEventRecord(cEv[4], s0);
    URGENT(4);

    cudaStreamWaitEvent(s1, cEv[4], 0);
    DEFERT(2);  cudaEventRecord(tEv[2], s1);            // target 2 (mp=4..7)

    cudaStreamWaitEvent(s0, tEv[3], 0);
    RUN_CHAIN(3);  cudaEventRecord(cEv[3], s0);
    URGENT(3);

    cudaStreamWaitEvent(s1, cEv[3], 0);
    DEFERT(1);  cudaEventRecord(tEv[1], s1);            // target 1 (mp=3..7)

    cudaStreamWaitEvent(s0, tEv[2], 0);
    RUN_CHAIN(2);  cudaEventRecord(cEv[2], s0);
    URGENT(2);

    cudaStreamWaitEvent(s1, cEv[2], 0);
    DEFERT(0);  cudaEventRecord(tEv[0], s1);            // target 0 (mp=2..7)

    cudaStreamWaitEvent(s0, tEv[1], 0);
    RUN_CHAIN(1);  cudaEventRecord(cEv[1], s0);
    URGENT(1);

    // single pout for modules 1..7 (gs 513..1027) on s1
    cudaStreamWaitEvent(s1, cEv[1], 0);
    pout_kernel<<<515, 256, 0, s1>>>(fc_w, 513);
    cudaEventRecord(evJoin, s1);

    cudaStreamWaitEvent(s0, tEv[0], 0);
    RUN_CHAIN(0);

    cudaStreamWaitEvent(s0, evJoin, 0);
    assemble_fused<<<(NB * NT) / 8, 256, 0, s0>>>(fc_w, fc_b, out);

    #undef RUN_CHAIN
    #undef URGENT
    #undef DEFERT
}

// round 16
// speedup vs baseline: 1.0233x; 1.0233x over previous
#include <cuda_runtime.h>
#include <cuda_bf16.h>
#include <math.h>

// Clockwork RNN, hierarchically decomposed.
// B=128, T=512, I=2, H=1024, NM=8, MS=128.
// Round 16: exact R13 champion (per-piece deferred GEMM launches, eager
// per-module pouts on stream1) + ONE change: module-0 pout fused into the
// final assemble (removes a 513-CTA launch + g_pout roundtrip from the
// stream-0 tail).

#define NB   128
#define NT   512
#define NH   1024
#define NMOD 8
#define MSZ  128

__constant__ int c_TOFF[8] = {0, 513, 770, 899, 964, 997, 1014, 1023};
__constant__ long long c_GOFF[8] = {0, 0, 4210688, 8437760, 11632640,
                                    13795328, 15187968, 16072704};

__device__ __nv_bfloat16 g_trajH[16842752];   // bf16 hi plane
__device__ __nv_bfloat16 g_trajL[16842752];   // bf16 lo plane
__device__ __nv_bfloat16 g_WHi[NH * NH];
__device__ __nv_bfloat16 g_WLo[NH * NH];
__device__ float g_G[16646144];
__device__ float g_pout[1028 * NB * 2];

// helpers -------------------------------------------------------------------
__device__ __forceinline__ void fma2(unsigned long long& d,
                                     unsigned long long a,
                                     unsigned long long b) {
    asm("fma.rn.f32x2 %0, %1, %2, %0;" : "+l"(d) : "l"(a), "l"(b));
}
__device__ __forceinline__ unsigned long long add2(unsigned long long a,
                                                   unsigned long long b) {
    unsigned long long d;
    asm("add.rn.f32x2 %0, %1, %2;" : "=l"(d) : "l"(a), "l"(b));
    return d;
}
union U4 { float4 f; unsigned long long u[2]; };
union U2 { unsigned long long u; float2 f; };

__device__ __forceinline__ float fast_tanh(float v) {
    float e = __expf(2.f * v);
    return 1.f - __fdividef(2.f, e + 1.f);
}

__device__ __forceinline__ void cp16(unsigned int dst, const void* src) {
    asm volatile("cp.async.ca.shared.global [%0], [%1], 16;"
                 :: "r"(dst), "l"(src));
}
__device__ __forceinline__ void cp_commit() {
    asm volatile("cp.async.commit_group;");
}
__device__ __forceinline__ void cp_wait1() {
    asm volatile("cp.async.wait_group 1;" ::: "memory");
}
__device__ __forceinline__ void cp_wait0() {
    asm volatile("cp.async.wait_group 0;" ::: "memory");
}
__device__ __forceinline__ void ldm4(unsigned int& r0, unsigned int& r1,
                                     unsigned int& r2, unsigned int& r3,
                                     unsigned int addr) {
    asm volatile("ldmatrix.sync.aligned.m8n8.x4.shared.b16 {%0,%1,%2,%3}, [%4];"
                 : "=r"(r0), "=r"(r1), "=r"(r2), "=r"(r3) : "r"(addr));
}
__device__ __forceinline__ void mma16816(float* c, const unsigned int* a,
                                         unsigned int b0, unsigned int b1) {
    asm volatile(
        "mma.sync.aligned.m16n8k16.row.col.f32.bf16.bf16.f32 "
        "{%0,%1,%2,%3}, {%4,%5,%6,%7}, {%8,%9}, {%0,%1,%2,%3};"
        : "+f"(c[0]), "+f"(c[1]), "+f"(c[2]), "+f"(c[3])
        : "r"(a[0]), "r"(a[1]), "r"(a[2]), "r"(a[3]), "r"(b0), "r"(b1));
}

// ---------------------------------------------------------------------------
__global__ void wsplit_kernel(const float* __restrict__ W_hh) {
    const int i = (blockIdx.x * 256 + threadIdx.x) * 4;
    const float4 w = *(const float4*)(W_hh + i);
    __nv_bfloat16 h0 = __float2bfloat16(w.x), h1 = __float2bfloat16(w.y);
    __nv_bfloat16 h2 = __float2bfloat16(w.z), h3 = __float2bfloat16(w.w);
    *(__nv_bfloat162*)(g_WHi + i)     = __nv_bfloat162(h0, h1);
    *(__nv_bfloat162*)(g_WHi + i + 2) = __nv_bfloat162(h2, h3);
    *(__nv_bfloat162*)(g_WLo + i) = __nv_bfloat162(
        __float2bfloat16(w.x - __bfloat162float(h0)),
        __float2bfloat16(w.y - __bfloat162float(h1)));
    *(__nv_bfloat162*)(g_WLo + i + 2) = __nv_bfloat162(
        __float2bfloat16(w.z - __bfloat162float(h2)),
        __float2bfloat16(w.w - __bfloat162float(h3)));
}

// ---------------------------------------------------------------------------
// Sequential diagonal chain for module M (R13 version).
// ---------------------------------------------------------------------------
template <int M>
__global__ __launch_bounds__(MSZ, 1) void chain_kernel(
    const float* __restrict__ x,
    const float* __restrict__ W_ih,
    const float* __restrict__ W_hh,
    const float* __restrict__ enc_w) {
    const int b = blockIdx.x;
    const int r = threadIdx.x;
    const int mbase = M * MSZ;
    __shared__ float h_s[2][MSZ];
    __shared__ float Wst[64][132];

    unsigned long long Wp[MSZ / 2];
#pragma unroll
    for (int pass = 0; pass < 2; pass++) {
#pragma unroll
        for (int i = 0; i < 16; i++) {
            const int idx = i * 128 + r;
            const int row = idx >> 5;
            const int c4 = idx & 31;
            *(float4*)&Wst[row][c4 * 4] =
                *(const float4*)(W_hh +
                                 (size_t)(mbase + pass * 64 + row) * NH +
                                 mbase + c4 * 4);
        }
        __syncthreads();
        if ((r >> 6) == pass) {
            const int rr = r & 63;
#pragma unroll
            for (int c4 = 0; c4 < 32; c4++) {
                U4 w;
                w.f = *(const float4*)&Wst[rr][c4 * 4];
                Wp[2 * c4 + 0] = w.u[0];
                Wp[2 * c4 + 1] = w.u[1];
            }
        }
        __syncthreads();
    }

    const float wih0 = W_ih[(mbase + r) * 2 + 0];
    const float wih1 = W_ih[(mbase + r) * 2 + 1];

    const float x00 = x[(size_t)b * (NT + 1) * 2 + 0];
    const float x01 = x[(size_t)b * (NT + 1) * 2 + 1];
    const float h0v = x00 * enc_w[(mbase + r) * 2 + 0] +
                      x01 * enc_w[(mbase + r) * 2 + 1];
    const size_t tbase = ((size_t)c_TOFF[M] * NB + b) * MSZ;
    h_s[0][r] = h0v;
    {
        const __nv_bfloat16 hi = __float2bfloat16(h0v);
        g_trajH[tbase + r] = hi;
        g_trajL[tbase + r] = __float2bfloat16(h0v - __bfloat162float(hi));
    }
    __syncthreads();

    const int K = NT >> M;
    constexpr int NG = (NMOD - 1 - M) > 0 ? (NMOD - 1 - M) : 1;

    const float* gp[NG];
    float gg[NG];
#pragma unroll
    for (int mp = M + 1; mp < NMOD; mp++) {
        gp[mp - M - 1] = g_G + c_GOFF[mp] + (size_t)b * (mp * MSZ) +
                         mbase + r;
        gg[mp - M - 1] = *gp[mp - M - 1];
    }

    float xn0 = x[((size_t)b * (NT + 1) + 1) * 2 + 0];
    float xn1 = x[((size_t)b * (NT + 1) + 1) * 2 + 1];

    int p = 0;
    for (int k = 0; k < K; k++) {
        float gsum = xn0 * wih0 + xn1 * wih1;
#pragma unroll
        for (int mp = M + 1; mp < NMOD; mp++) gsum += gg[mp - M - 1];

        const int t2 = (k + 1) << M;
        float xt0 = 0.f, xt1 = 0.f;
        if (k + 1 < K) {
            xt0 = x[((size_t)b * (NT + 1) + (t2 + 1)) * 2 + 0];
            xt1 = x[((size_t)b * (NT + 1) + (t2 + 1)) * 2 + 1];
        }
        float gt[NG];
#pragma unroll
        for (int mp = M + 1; mp < NMOD; mp++) {
            const int i = mp - M - 1;
            const bool trig = (((t2 - 1) & ((1 << mp) - 1)) < (1 << M));
            if (trig) {
                gp[i] += (size_t)NB * mp * MSZ;
                gt[i] = __ldg(gp[i]);
            } else {
                gt[i] = gg[i];
            }
        }

        unsigned long long acc[8] = {0, 0, 0, 0, 0, 0, 0, 0};
        const float4* h4 = (const float4*)h_s[p];
#pragma unroll
        for (int c4 = 0; c4 < MSZ / 4; c4++) {
            U4 hv;
            hv.f = h4[c4];
            fma2(acc[(2 * c4) & 7], Wp[2 * c4], hv.u[0]);
            fma2(acc[(2 * c4 + 1) & 7], Wp[2 * c4 + 1], hv.u[1]);
        }
        acc[0] = add2(acc[0], acc[1]);
        acc[2] = add2(acc[2], acc[3]);
        acc[4] = add2(acc[4], acc[5]);
        acc[6] = add2(acc[6], acc[7]);
        acc[0] = add2(acc[0], acc[2]);
        acc[4] = add2(acc[4], acc[6]);
        acc[0] = add2(acc[0], acc[4]);
        U2 a;
        a.u = acc[0];
        const float hn = fast_tanh(a.f.x + a.f.y + gsum);

        h_s[p ^ 1][r] = hn;
        const size_t so = tbase + (size_t)(k + 1) * (NB * MSZ) + r;
        const __nv_bfloat16 hi = __float2bfloat16(hn);
        g_trajH[so] = hi;
        g_trajL[so] = __float2bfloat16(hn - __bfloat162float(hi));
        __syncthreads();
        p ^= 1;

        xn0 = xt0; xn1 = xt1;
#pragma unroll
        for (int mp = M + 1; mp < NMOD; mp++) gg[mp - M - 1] = gt[mp - M - 1];
    }
}

// ---------------------------------------------------------------------------
// Tensor-core split-GEMM piece (R13 champion):
//   G_{mp}[:, tgt-block] = Traj_{mp} @ W_hh[tgt-block rows, mp-cols]^T
// 64x64 tile, 128 thr, 8 K-chunks of 16, fused bf16-split (24 mma/chunk),
// 3-stage cp.async ring, one barrier per chunk.
// ---------------------------------------------------------------------------
__global__ __launch_bounds__(128, 4) void g_tcp(int mp, int tgt) {
    __shared__ __align__(16) __nv_bfloat16 AH[3][64][24];
    __shared__ __align__(16) __nv_bfloat16 AL[3][64][24];
    __shared__ __align__(16) __nv_bfloat16 BH[3][64][24];
    __shared__ __align__(16) __nv_bfloat16 BL[3][64][24];
    const int N = mp * MSZ;
    float* C = g_G + c_GOFF[mp] + tgt * MSZ;
    const int row0 = blockIdx.x * 64;
    const int n0 = blockIdx.y * 64;
    const int tid = threadIdx.x;
    const int w = tid >> 5;
    const int l = tid & 31;

    const size_t abase = (size_t)c_TOFF[mp] * (NB * MSZ);
    const __nv_bfloat16* AHsrc = g_trajH + abase;
    const __nv_bfloat16* ALsrc = g_trajL + abase;

    const int crow = tid >> 1, half = tid & 1;
    const unsigned int sAH =
        (unsigned int)__cvta_generic_to_shared(&AH[0][crow][half * 8]);
    const unsigned int sAL =
        (unsigned int)__cvta_generic_to_shared(&AL[0][crow][half * 8]);
    const unsigned int sBH =
        (unsigned int)__cvta_generic_to_shared(&BH[0][crow][half * 8]);
    const unsigned int sBL =
        (unsigned int)__cvta_generic_to_shared(&BL[0][crow][half * 8]);
    const unsigned int STG = 64 * 24 * 2;

    const size_t aoff = (size_t)(row0 + crow) * MSZ + half * 8;
    const size_t boff = (size_t)(tgt * MSZ + n0 + crow) * NH + mp * MSZ +
                        half * 8;

    #define LOAD_CHUNK(st, c)                                   \
        do {                                                    \
            cp16(sAH + (st) * STG, AHsrc + aoff + (c) * 16);    \
            cp16(sAL + (st) * STG, ALsrc + aoff + (c) * 16);    \
            cp16(sBH + (st) * STG, g_WHi + boff + (c) * 16);    \
            cp16(sBL + (st) * STG, g_WLo + boff + (c) * 16);    \
            cp_commit();                                        \
        } while (0)

    LOAD_CHUNK(0, 0);
    LOAD_CHUNK(1, 1);

    const int rowA = l & 15, kOffA = (l >> 4) * 8;
    const unsigned int aAddrH = (unsigned int)__cvta_generic_to_shared(
        &AH[0][w * 16 + rowA][kOffA]);
    const unsigned int aAddrL = (unsigned int)__cvta_generic_to_shared(
        &AL[0][w * 16 + rowA][kOffA]);
    const int gB = l >> 3, r8 = l & 7;
    const int nB = (gB >> 1) * 8 + r8, kOffB = (gB & 1) * 8;
    unsigned int bAddrH[4], bAddrL[4];
#pragma unroll
    for (int j = 0; j < 4; j++) {
        bAddrH[j] = (unsigned int)__cvta_generic_to_shared(
            &BH[0][j * 16 + nB][kOffB]);
        bAddrL[j] = (unsigned int)__cvta_generic_to_shared(
            &BL[0][j * 16 + nB][kOffB]);
    }

    float acc[8][4];
#pragma unroll
    for (int i = 0; i < 8; i++)
#pragma unroll
        for (int j = 0; j < 4; j++) acc[i][j] = 0.f;

#pragma unroll
    for (int c = 0; c < 8; c++) {
        if (c < 7) cp_wait1(); else cp_wait0();
        __syncthreads();
        if (c + 2 < 8) LOAD_CHUNK((c + 2) % 3, c + 2);

        const unsigned int so = (c % 3) * STG;
        unsigned int ah[4], al[4];
        ldm4(ah[0], ah[1], ah[2], ah[3], aAddrH + so);
        ldm4(al[0], al[1], al[2], al[3], aAddrL + so);
#pragma unroll
        for (int j = 0; j < 4; j++) {
            unsigned int h0, h1, h2, h3, q0, q1, q2, q3;
            ldm4(h0, h1, h2, h3, bAddrH[j] + so);
            ldm4(q0, q1, q2, q3, bAddrL[j] + so);
            mma16816(acc[2 * j], ah, h0, h1);
            mma16816(acc[2 * j + 1], ah, h2, h3);
            mma16816(acc[2 * j], ah, q0, q1);
            mma16816(acc[2 * j + 1], ah, q2, q3);
            mma16816(acc[2 * j], al, h0, h1);
            mma16816(acc[2 * j + 1], al, h2, h3);
        }
    }

    const int orow = row0 + w * 16 + (l >> 2);
    const int ocol = n0 + 2 * (l & 3);
#pragma unroll
    for (int cb = 0; cb < 8; cb++) {
        float2 v0 = {acc[cb][0], acc[cb][1]};
        float2 v1 = {acc[cb][2], acc[cb][3]};
        *(float2*)&C[(size_t)orow * N + ocol + cb * 8] = v0;
        *(float2*)&C[(size_t)(orow + 8) * N + ocol + cb * 8] = v1;
    }
    #undef LOAD_CHUNK
}

// ---------------------------------------------------------------------------
// fc partials for one module's state range; h reconstructed from hi+lo.
// ---------------------------------------------------------------------------
__global__ __launch_bounds__(256) void pout_kernel(
    const float* __restrict__ fc_w, int gs0, int m) {
    const int gs = gs0 + blockIdx.x;
    const int warp = threadIdx.x >> 5;
    const int lane = threadIdx.x & 31;
    const int col = m * MSZ + lane * 4;
    const float4 w0 = *(const float4*)(fc_w + col);
    const float4 w1 = *(const float4*)(fc_w + NH + col);
    const size_t sbase = (size_t)gs * (NB * MSZ);

    for (int b = warp; b < NB; b += 8) {
        const size_t o = sbase + (size_t)b * MSZ + lane * 4;
        const __nv_bfloat162 h0 = *(const __nv_bfloat162*)(g_trajH + o);
        const __nv_bfloat162 h1 = *(const __nv_bfloat162*)(g_trajH + o + 2);
        const __nv_bfloat162 l0 = *(const __nv_bfloat162*)(g_trajL + o);
        const __nv_bfloat162 l1 = *(const __nv_bfloat162*)(g_trajL + o + 2);
        const float vx = __low2float(h0) + __low2float(l0);
        const float vy = __high2float(h0) + __high2float(l0);
        const float vz = __low2float(h1) + __low2float(l1);
        const float vw = __high2float(h1) + __high2float(l1);
        float a0 = vx * w0.x + vy * w0.y + vz * w0.z + vw * w0.w;
        float a1 = vx * w1.x + vy * w1.y + vz * w1.z + vw * w1.w;
#pragma unroll
        for (int off = 16; off > 0; off >>= 1) {
            a0 += __shfl_xor_sync(0xffffffffu, a0, off);
            a1 += __shfl_xor_sync(0xffffffffu, a1, off);
        }
        if (lane == 0) {
            g_pout[((size_t)gs * NB + b) * 2 + 0] = a0;
            g_pout[((size_t)gs * NB + b) * 2 + 1] = a1;
        }
    }
}

// ---------------------------------------------------------------------------
// Fused assemble: warp per (b,t). Lanes compute the module-0 dot slice;
// lanes 1..7 additionally add module-m pout pairs; lane 0 adds fc_b.
// (validated in R15: rel_err 3.9026e-6)
// ---------------------------------------------------------------------------
__global__ __launch_bounds__(256) void assemble_fused(
    const float* __restrict__ fc_w, const float* __restrict__ fc_b,
    float* __restrict__ out) {
    const int widx = blockIdx.x * 8 + (threadIdx.x >> 5);   // 0..65535
    const int lane = threadIdx.x & 31;
    const int b = widx >> 9;
    const int t = widx & 511;

    // module-0 dot slice (state gs = t+1, cols lane*4..lane*4+3)
    const size_t o = (size_t)(t + 1) * (NB * MSZ) + (size_t)b * MSZ + lane * 4;
    const __nv_bfloat162 h0 = *(const __nv_bfloat162*)(g_trajH + o);
    const __nv_bfloat162 h1 = *(const __nv_bfloat162*)(g_trajH + o + 2);
    const __nv_bfloat162 l0 = *(const __nv_bfloat162*)(g_trajL + o);
    const __nv_bfloat162 l1 = *(const __nv_bfloat162*)(g_trajL + o + 2);
    const float vx = __low2float(h0) + __low2float(l0);
    const float vy = __high2float(h0) + __high2float(l0);
    const float vz = __low2float(h1) + __low2float(l1);
    const float vw = __high2float(h1) + __high2float(l1);
    const float4 w0 = *(const float4*)(fc_w + lane * 4);
    const float4 w1 = *(const float4*)(fc_w + NH + lane * 4);
    float a0 = vx * w0.x + vy * w0.y + vz * w0.z + vw * w0.w;
    float a1 = vx * w1.x + vy * w1.y + vz * w1.z + vw * w1.w;

    if (lane >= 1 && lane <= 7) {
        const int m = lane;
        const int gs = c_TOFF[m] + (t >> m) + 1;
        const float2 pv = *(const float2*)&g_pout[((size_t)gs * NB + b) * 2];
        a0 += pv.x;
        a1 += pv.y;
    } else if (lane == 0) {
        a0 += fc_b[0];
        a1 += fc_b[1];
    }

#pragma unroll
    for (int off = 16; off > 0; off >>= 1) {
        a0 += __shfl_xor_sync(0xffffffffu, a0, off);
        a1 += __shfl_xor_sync(0xffffffffu, a1, off);
    }
    if (lane == 0) {
        float2 v = {a0, a1};
        *(float2*)&out[(size_t)widx * 2] = v;
    }
}

// ---------------------------------------------------------------------------
// Deadline-ordered two-stream schedule (R13 champion layout).
// ---------------------------------------------------------------------------
static const int h_TOFF[8] = {0, 513, 770, 899, 964, 997, 1014, 1023};
static const int h_S[8] = {513, 257, 129, 65, 33, 17, 9, 5};

extern "C" void kernel_launch(void* const* d_in, const int* in_sizes, int n_in,
                              void* d_out, int out_size) {
    const float* x     = (const float*)d_in[0];
    const float* W_ih  = (const float*)d_in[1];
    const float* W_hh  = (const float*)d_in[2];
    const float* fc_w  = (const float*)d_in[3];
    const float* fc_b  = (const float*)d_in[4];
    const float* enc_w = (const float*)d_in[5];
    float* out = (float*)d_out;

    static cudaStream_t s1 = nullptr;
    static cudaEvent_t evFork, evJoin, wEv, cEv[8], tEv[8];
    if (!s1) {
        cudaStreamCreateWithFlags(&s1, cudaStreamNonBlocking);
        cudaEventCreateWithFlags(&evFork, cudaEventDisableTiming);
        cudaEventCreateWithFlags(&evJoin, cudaEventDisableTiming);
        cudaEventCreateWithFlags(&wEv, cudaEventDisableTiming);
        for (int i = 0; i < 8; i++) {
            cudaEventCreateWithFlags(&cEv[i], cudaEventDisableTiming);
            cudaEventCreateWithFlags(&tEv[i], cudaEventDisableTiming);
        }
    }
    cudaStream_t s0 = 0;

    cudaEventRecord(evFork, s0);
    cudaStreamWaitEvent(s1, evFork, 0);

    #define RUN_CHAIN(M) chain_kernel<M><<<NB, MSZ, 0, s0>>>(x, W_ih, W_hh, enc_w)
    #define URGENT(MP)   g_tcp<<<dim3(2 * h_S[MP], 2), 128, 0, s0>>>(MP, (MP) - 1)
    #define DEFER(MP, MT) g_tcp<<<dim3(2 * h_S[MP], 2), 128, 0, s1>>>(MP, MT)
    #define POUT1(M, SS) pout_kernel<<<h_S[M], 256, 0, SS>>>(fc_w, h_TOFF[M], M)

    wsplit_kernel<<<1024, 256, 0, s1>>>(W_hh);
    cudaEventRecord(wEv, s1);

    RUN_CHAIN(7);  cudaEventRecord(cEv[7], s0);
    cudaStreamWaitEvent(s0, wEv, 0);
    URGENT(7);

    cudaStreamWaitEvent(s1, cEv[7], 0);
    DEFER(7, 5);  cudaEventRecord(tEv[5], s1);          // target 5 complete

    RUN_CHAIN(6);  cudaEventRecord(cEv[6], s0);
    URGENT(6);

    DEFER(7, 4);
    cudaStreamWaitEvent(s1, cEv[6], 0);
    DEFER(6, 4);  cudaEventRecord(tEv[4], s1);          // target 4 complete

    cudaStreamWaitEvent(s0, tEv[5], 0);
    RUN_CHAIN(5);  cudaEventRecord(cEv[5], s0);
    URGENT(5);

    DEFER(7, 3); DEFER(6, 3);
    cudaStreamWaitEvent(s1, cEv[5], 0);
    DEFER(5, 3);  cudaEventRecord(tEv[3], s1);          // target 3 complete

    cudaStreamWaitEvent(s0, tEv[4], 0);
    RUN_CHAIN(4);  cudaEventRecord(cEv[4], s0);
    URGENT(4);

    DEFER(7, 2); DEFER(6, 2); DEFER(5, 2);
    cudaStreamWaitEvent(s1, cEv[4], 0);
    DEFER(4, 2);  cudaEventRecord(tEv[2], s1);          // target 2 complete

    cudaStreamWaitEvent(s0, tEv[3], 0);
    RUN_CHAIN(3);  cudaEventRecord(cEv[3], s0);
    URGENT(3);

    DEFER(7, 1); DEFER(6, 1); DEFER(5, 1); DEFER(4, 1);
    cudaStreamWaitEvent(s1, cEv[3], 0);
    DEFER(3, 1);  cudaEventRecord(tEv[1], s1);          // target 1 complete

    cudaStreamWaitEvent(s0, tEv[2], 0);
    RUN_CHAIN(2);  cudaEventRecord(cEv[2], s0);
    URGENT(2);

    DEFER(7, 0); DEFER(6, 0); DEFER(5, 0); DEFER(4, 0); DEFER(3, 0);
    cudaStreamWaitEvent(s1, cEv[2], 0);
    DEFER(2, 0);  cudaEventRecord(tEv[0], s1);          // target 0 complete

    cudaStreamWaitEvent(s0, tEv[1], 0);
    RUN_CHAIN(1);  cudaEventRecord(cEv[1], s0);
    URGENT(1);

    // eager per-module pouts (R13 layout)
    POUT1(7, s1); POUT1(6, s1); POUT1(5, s1); POUT1(4, s1);
    POUT1(3, s1); POUT1(2, s1);
    cudaStreamWaitEvent(s1, cEv[1], 0);
    POUT1(1, s1);
    cudaEventRecord(evJoin, s1);

    cudaStreamWaitEvent(s0, tEv[0], 0);
    RUN_CHAIN(0);

    cudaStreamWaitEvent(s0, evJoin, 0);
    assemble_fused<<<(NB * NT) / 8, 256, 0, s0>>>(fc_w, fc_b, out);

    #undef RUN_CHAIN
    #undef URGENT
    #undef DEFER
    #undef POUT1
}